// round 16
// baseline (speedup 1.0000x reference)
#include <cuda_runtime.h>
#include <cuda_bf16.h>
#include <math.h>

#define BB 4
#define SS 2048
#define EMB 1024
#define HEADS 16
#define HDIM 64
#define MROWS (BB * SS)   // 8192

typedef unsigned long long u64;
typedef unsigned int u32;

#define SWZ(o) ((o) ^ (((o) >> 3) & 0x70))   // SW128 byte swizzle

// ---------------- baseline async + mma helpers (sm_103-safe) ----------------
__device__ __forceinline__ u32 smem_u32(const void* p) {
    u32 a; asm("{ .reg .u64 t; cvta.to.shared.u64 t, %1; cvt.u32.u64 %0, t; }" : "=r"(a) : "l"(p));
    return a;
}
__device__ __forceinline__ void cp16(u32 dst, const void* src) {
    asm volatile("cp.async.cg.shared.global [%0], [%1], 16;" :: "r"(dst), "l"(src) : "memory");
}
__device__ __forceinline__ void cp_commit() { asm volatile("cp.async.commit_group;" ::: "memory"); }
__device__ __forceinline__ void cp_wait2()  { asm volatile("cp.async.wait_group 2;"  ::: "memory"); }
__device__ __forceinline__ void cp_wait1()  { asm volatile("cp.async.wait_group 1;"  ::: "memory"); }
__device__ __forceinline__ void cp_wait0()  { asm volatile("cp.async.wait_group 0;"  ::: "memory"); }

__device__ __forceinline__ void ldm_x4(u32* r, u32 addr) {
    asm volatile("ldmatrix.sync.aligned.m8n8.x4.shared.b16 {%0,%1,%2,%3}, [%4];"
        : "=r"(r[0]), "=r"(r[1]), "=r"(r[2]), "=r"(r[3]) : "r"(addr));
}
__device__ __forceinline__ void ldm_x2(u32* r, u32 addr) {
    asm volatile("ldmatrix.sync.aligned.m8n8.x2.shared.b16 {%0,%1}, [%2];"
        : "=r"(r[0]), "=r"(r[1]) : "r"(addr));
}
__device__ __forceinline__ void ldm_x2t(u32* r, u32 addr) {
    asm volatile("ldmatrix.sync.aligned.m8n8.x2.trans.shared.b16 {%0,%1}, [%2];"
        : "=r"(r[0]), "=r"(r[1]) : "r"(addr));
}
__device__ __forceinline__ void mma_bf16(float* c, const u32* a, const u32* b) {
    asm volatile(
        "mma.sync.aligned.m16n8k16.row.col.f32.bf16.bf16.f32 "
        "{%0,%1,%2,%3}, {%4,%5,%6,%7}, {%8,%9}, {%0,%1,%2,%3};"
        : "+f"(c[0]), "+f"(c[1]), "+f"(c[2]), "+f"(c[3])
        : "r"(a[0]), "r"(a[1]), "r"(a[2]), "r"(a[3]), "r"(b[0]), "r"(b[1]));
}
// pack (s0, s1) -> bf16x2 hi + bf16x2 residual lo
__device__ __forceinline__ void pack_hilo(float s0, float s1, u32& ph, u32& pl) {
    u32 h; asm("cvt.rn.bf16x2.f32 %0, %1, %2;" : "=r"(h) : "f"(s1), "f"(s0));
    const float h0 = __uint_as_float(h << 16);
    const float h1 = __uint_as_float(h & 0xffff0000u);
    u32 l; asm("cvt.rn.bf16x2.f32 %0, %1, %2;" : "=r"(l) : "f"(s1 - h1), "f"(s0 - h0));
    ph = h; pl = l;
}

// ---------------- scratch ----------------
__device__ __nv_bfloat16 g_ahi[MROWS * EMB];
__device__ __nv_bfloat16 g_alo[MROWS * EMB];
__device__ __nv_bfloat16 g_wthi[EMB * EMB];
__device__ __nv_bfloat16 g_wtlo[EMB * EMB];
__device__ __nv_bfloat16 g_qhi[MROWS * EMB];
__device__ __nv_bfloat16 g_qlo[MROWS * EMB];
__device__ __nv_bfloat16 g_khi[MROWS * EMB];
__device__ __nv_bfloat16 g_klo[MROWS * EMB];
__device__ __nv_bfloat16 g_vhi[MROWS * EMB];
__device__ __nv_bfloat16 g_vlo[MROWS * EMB];

// ---------------- bf16 split preps ----------------
__device__ __forceinline__ unsigned short bfbits(float x) {
    __nv_bfloat16 h = __float2bfloat16(x);
    return reinterpret_cast<unsigned short&>(h);
}
__device__ __forceinline__ float bfval(unsigned short b) {
    __nv_bfloat16 h = reinterpret_cast<__nv_bfloat16&>(b);
    return __bfloat162float(h);
}

__global__ __launch_bounds__(256) void split_bf16(
    const float* __restrict__ x, __nv_bfloat16* __restrict__ hi,
    __nv_bfloat16* __restrict__ lo, int n4)
{
    int i = blockIdx.x * blockDim.x + threadIdx.x;
    const int stride = gridDim.x * blockDim.x;
    for (; i < n4; i += stride) {
        const float4 v = ((const float4*)x)[i];
        unsigned short h0 = bfbits(v.x), h1 = bfbits(v.y), h2 = bfbits(v.z), h3 = bfbits(v.w);
        unsigned short l0 = bfbits(v.x - bfval(h0)), l1 = bfbits(v.y - bfval(h1));
        unsigned short l2 = bfbits(v.z - bfval(h2)), l3 = bfbits(v.w - bfval(h3));
        ((uint2*)hi)[i] = make_uint2((u32)h0 | ((u32)h1 << 16), (u32)h2 | ((u32)h3 << 16));
        ((uint2*)lo)[i] = make_uint2((u32)l0 | ((u32)l1 << 16), (u32)l2 | ((u32)l3 << 16));
    }
}

__global__ void transpose_split(
    const float* __restrict__ W, __nv_bfloat16* __restrict__ hi,
    __nv_bfloat16* __restrict__ lo)
{
    __shared__ float t[32][33];
    const int k0 = blockIdx.y * 32, n0 = blockIdx.x * 32;
    const int x = threadIdx.x, y0 = threadIdx.y;
#pragma unroll
    for (int i = 0; i < 4; i++) t[y0 + i * 8][x] = W[(size_t)(k0 + y0 + i * 8) * EMB + n0 + x];
    __syncthreads();
#pragma unroll
    for (int i = 0; i < 4; i++) {
        const int nn = y0 + i * 8;
        const float v = t[x][nn];
        const unsigned short h = bfbits(v);
        const unsigned short l = bfbits(v - bfval(h));
        hi[(size_t)(n0 + nn) * EMB + k0 + x] = reinterpret_cast<const __nv_bfloat16&>(h);
        lo[(size_t)(n0 + nn) * EMB + k0 + x] = reinterpret_cast<const __nv_bfloat16&>(l);
    }
}

// ---------------- mma.sync GEMM (bf16x3) ----------------
#define GEMM_NIT 16
#define STAGE_BYTES 65536
#define GEMM_SMEM (2 * STAGE_BYTES)

__device__ __forceinline__ void gemm_load_stage(
    u32 st, const __nv_bfloat16* __restrict__ Ahi, const __nv_bfloat16* __restrict__ Alo,
    const __nv_bfloat16* __restrict__ Bhi, const __nv_bfloat16* __restrict__ Blo,
    int m0, int n0, int k0, int tid)
{
#pragma unroll
    for (int i = 0; i < 4; i++) {
        const int c = tid + i * 256;
        const int row = c >> 3, col16 = c & 7;
        const u32 sw = (u32)SWZ(row * 128 + col16 * 16);
        const size_t ga = (size_t)(m0 + row) * EMB + k0 + col16 * 8;
        const size_t gb = (size_t)(n0 + row) * EMB + k0 + col16 * 8;
        cp16(st +     0 + sw, Ahi + ga);
        cp16(st + 16384 + sw, Alo + ga);
        cp16(st + 32768 + sw, Bhi + gb);
        cp16(st + 49152 + sw, Blo + gb);
    }
}

__global__ __launch_bounds__(256)
void gemm_mma(const __nv_bfloat16* __restrict__ Ahi, const __nv_bfloat16* __restrict__ Alo,
              const __nv_bfloat16* __restrict__ Bhi, const __nv_bfloat16* __restrict__ Blo,
              const float* __restrict__ bias, float* __restrict__ C,
              __nv_bfloat16* __restrict__ Chi, __nv_bfloat16* __restrict__ Clo,
              float scale, int split_mode)
{
    extern __shared__ __align__(1024) char smem[];
    const u32 sb = smem_u32(smem);
    const int tid = threadIdx.x;
    const int lane = tid & 31, wid = tid >> 5;
    const int wm = wid & 1, wn = wid >> 1;
    const int m0 = blockIdx.y * 128, n0 = blockIdx.x * 128;

    float acc[4][4][4];
#pragma unroll
    for (int mt = 0; mt < 4; mt++)
#pragma unroll
        for (int nt = 0; nt < 4; nt++)
#pragma unroll
            for (int e = 0; e < 4; e++) acc[mt][nt][e] = 0.f;

    const int a_row = (lane & 15), a_kb = (lane >> 4) * 16;
    const int b_row = (lane & 7),  b_kb = ((lane >> 3) & 1) * 16;

    gemm_load_stage(sb,               Ahi, Alo, Bhi, Blo, m0, n0, 0,  tid); cp_commit();
    gemm_load_stage(sb + STAGE_BYTES, Ahi, Alo, Bhi, Blo, m0, n0, 64, tid); cp_commit();

    for (int it = 0; it < GEMM_NIT; it++) {
        const u32 stg = sb + (it & 1) * STAGE_BYTES;
        if (it >= GEMM_NIT - 2) cp_wait0(); else cp_wait1();
        __syncthreads();

        const u32 sAh = stg, sAl = stg + 16384, sBh = stg + 32768, sBl = stg + 49152;
#pragma unroll
        for (int ks = 0; ks < 4; ks++) {
            u32 ah[4][4], al[4][4], bh[4][2], bl[4][2];
#pragma unroll
            for (int mt = 0; mt < 4; mt++) {
                const u32 off = (u32)SWZ((wm * 64 + mt * 16 + a_row) * 128 + ks * 32 + a_kb);
                ldm_x4(ah[mt], sAh + off);
                ldm_x4(al[mt], sAl + off);
            }
#pragma unroll
            for (int nt = 0; nt < 4; nt++) {
                const u32 off = (u32)SWZ((wn * 32 + nt * 8 + b_row) * 128 + ks * 32 + b_kb);
                ldm_x2(bh[nt], sBh + off);
                ldm_x2(bl[nt], sBl + off);
            }
#pragma unroll
            for (int mt = 0; mt < 4; mt++)
#pragma unroll
                for (int nt = 0; nt < 4; nt++) {
                    mma_bf16(acc[mt][nt], ah[mt], bh[nt]);
                    mma_bf16(acc[mt][nt], ah[mt], bl[nt]);
                    mma_bf16(acc[mt][nt], al[mt], bh[nt]);
                }
        }
        __syncthreads();
        if (it + 2 < GEMM_NIT) {
            gemm_load_stage(stg, Ahi, Alo, Bhi, Blo, m0, n0, (it + 2) * 64, tid);
            cp_commit();
        }
    }

#pragma unroll
    for (int mt = 0; mt < 4; mt++) {
        const int r0 = m0 + wm * 64 + mt * 16 + (lane >> 2);
#pragma unroll
        for (int nt = 0; nt < 4; nt++) {
            const int cc = n0 + wn * 32 + nt * 8 + (lane & 3) * 2;
            const float2 bb = *(const float2*)&bias[cc];
#pragma unroll
            for (int half = 0; half < 2; half++) {
                const int m = r0 + half * 8;
                const float v0 = (acc[mt][nt][half * 2 + 0] + bb.x) * scale;
                const float v1 = (acc[mt][nt][half * 2 + 1] + bb.y) * scale;
                if (split_mode) {   // bf16 hi/lo, (B,H,S,D) layout
                    const int b = m >> 11, s2 = m & 2047;
                    const int h = cc >> 6, dd = cc & 63;
                    u32 ph, pl; pack_hilo(v0, v1, ph, pl);
                    const size_t off = (((size_t)(b * HEADS + h) * SS) + s2) * HDIM + dd;
                    *(u32*)&Chi[off] = ph;
                    *(u32*)&Clo[off] = pl;
                } else {
                    *(float2*)&C[(size_t)m * EMB + cc] = make_float2(v0, v1);
                }
            }
        }
    }
}

// ---------------- flash attention via mma.sync (bf16x3) ----------------
// CTA: 128 q-rows x (b,h). 8 warps, warp w owns q rows [w*16, w*16+16).
// smem: Qhi/Qlo 32K + 2 stages x (Khi,Klo,Vhi,Vlo 8K each) = 96K.
#define FA_SMEM (32768 + 65536)

__device__ __forceinline__ void fa_load_stage(
    u32 st, const __nv_bfloat16* Kh, const __nv_bfloat16* Kl,
    const __nv_bfloat16* Vh, const __nv_bfloat16* Vl, size_t gbase, int tid)
{
#pragma unroll
    for (int i = 0; i < 2; i++) {
        const int c = tid + i * 256;              // 0..511
        const int row = c >> 3, col16 = c & 7;
        const u32 sw = (u32)SWZ(row * 128 + col16 * 16);
        const size_t g = gbase + (size_t)row * HDIM + col16 * 8;
        cp16(st +     0 + sw, Kh + g);
        cp16(st +  8192 + sw, Kl + g);
        cp16(st + 16384 + sw, Vh + g);
        cp16(st + 24576 + sw, Vl + g);
    }
}

__global__ __launch_bounds__(256, 1)
void flash_mma(const __nv_bfloat16* __restrict__ Qh_, const __nv_bfloat16* __restrict__ Ql_,
               const __nv_bfloat16* __restrict__ Kh_, const __nv_bfloat16* __restrict__ Kl_,
               const __nv_bfloat16* __restrict__ Vh_, const __nv_bfloat16* __restrict__ Vl_,
               const u32* __restrict__ mask,
               __nv_bfloat16* __restrict__ Ohi, __nv_bfloat16* __restrict__ Olo)
{
    extern __shared__ __align__(1024) char smem[];
    __shared__ float mb[2][64];
    const u32 sb = smem_u32(smem);
    const int tid = threadIdx.x;
    const int lane = tid & 31, w = tid >> 5;
    const int bh = blockIdx.y, b = bh >> 4, h = bh & 15;
    const int q0 = blockIdx.x * 128;

    const size_t qbase  = ((size_t)bh * SS + q0) * HDIM;
    const size_t kvbase = (size_t)bh * SS * HDIM;
    const u32 sQh = sb, sQl = sb + 16384;
    const u32 stg0 = sb + 32768, stg1 = sb + 65536;

    // Q tile loads (hi+lo): 2048 chunks / 256 thr = 8 each
#pragma unroll
    for (int i = 0; i < 4; i++) {
        const int c = tid + i * 256;
        const int row = c >> 3, col16 = c & 7;
        const u32 sw = (u32)SWZ(row * 128 + col16 * 16);
        const size_t g = qbase + (size_t)row * HDIM + col16 * 8;
        cp16(sQh + sw, Qh_ + g);
        cp16(sQl + sw, Ql_ + g);
    }
    cp_commit();
    fa_load_stage(stg0, Kh_, Kl_, Vh_, Vl_, kvbase, tid);          cp_commit();
    if (tid < 64) mb[0][tid] = mask[(size_t)b * SS + tid] ? 0.f : -1e30f;
    fa_load_stage(stg1, Kh_, Kl_, Vh_, Vl_, kvbase + 64 * HDIM, tid); cp_commit();
    if (tid < 64) mb[1][tid] = mask[(size_t)b * SS + 64 + tid] ? 0.f : -1e30f;

    cp_wait2();     // Q group done
    __syncthreads();

    // Q fragments (loop-invariant)
    u32 qh[4][4], ql[4][4];
    const int a_row = (lane & 15), a_kb = (lane >> 4) * 16;
#pragma unroll
    for (int ks = 0; ks < 4; ks++) {
        const u32 off = (u32)SWZ((w * 16 + a_row) * 128 + ks * 32 + a_kb);
        ldm_x4(qh[ks], sQh + off);
        ldm_x4(ql[ks], sQl + off);
    }

    float m_i[2] = { -INFINITY, -INFINITY }, l_i[2] = { 0.f, 0.f };
    float o[8][4];
#pragma unroll
    for (int nt = 0; nt < 8; nt++)
#pragma unroll
        for (int e = 0; e < 4; e++) o[nt][e] = 0.f;

    const int b_row = (lane & 7), b_kb = ((lane >> 3) & 1) * 16;

    for (int kb = 0; kb < 32; kb++) {
        const int st = kb & 1;
        const u32 stg = st ? stg1 : stg0;
        if (kb >= 30) cp_wait0(); else cp_wait1();
        __syncthreads();

        const u32 sKh = stg, sKl = stg + 8192, sVh = stg + 16384, sVl = stg + 24576;

        // --- QK^T (3-pass bf16x3), scores in fp32 acc regs ---
        float s[8][4];
#pragma unroll
        for (int nt = 0; nt < 8; nt++)
#pragma unroll
            for (int e = 0; e < 4; e++) s[nt][e] = 0.f;

#pragma unroll
        for (int ks = 0; ks < 4; ks++) {
            u32 kh[8][2], kl[8][2];
#pragma unroll
            for (int nt = 0; nt < 8; nt++) {
                const u32 off = (u32)SWZ((nt * 8 + b_row) * 128 + ks * 32 + b_kb);
                ldm_x2(kh[nt], sKh + off);
                ldm_x2(kl[nt], sKl + off);
            }
#pragma unroll
            for (int nt = 0; nt < 8; nt++) {
                mma_bf16(s[nt], qh[ks], kh[nt]);
                mma_bf16(s[nt], qh[ks], kl[nt]);
                mma_bf16(s[nt], ql[ks], kh[nt]);
            }
        }

        // --- mask bias ---
#pragma unroll
        for (int nt = 0; nt < 8; nt++) {
            const int kc = nt * 8 + (lane & 3) * 2;
            const float c0 = mb[st][kc], c1 = mb[st][kc + 1];
            s[nt][0] += c0; s[nt][1] += c1; s[nt][2] += c0; s[nt][3] += c1;
        }

        // --- online softmax (rows r=lane>>2 and r+8; row group = 4 lanes) ---
        float rm0 = -INFINITY, rm1 = -INFINITY;
#pragma unroll
        for (int nt = 0; nt < 8; nt++) {
            rm0 = fmaxf(rm0, fmaxf(s[nt][0], s[nt][1]));
            rm1 = fmaxf(rm1, fmaxf(s[nt][2], s[nt][3]));
        }
        rm0 = fmaxf(rm0, __shfl_xor_sync(0xffffffffu, rm0, 1));
        rm0 = fmaxf(rm0, __shfl_xor_sync(0xffffffffu, rm0, 2));
        rm1 = fmaxf(rm1, __shfl_xor_sync(0xffffffffu, rm1, 1));
        rm1 = fmaxf(rm1, __shfl_xor_sync(0xffffffffu, rm1, 2));
        const float nm0 = fmaxf(m_i[0], rm0), nm1 = fmaxf(m_i[1], rm1);
        const float corr0 = __expf(m_i[0] - nm0), corr1 = __expf(m_i[1] - nm1);
        float rs0 = 0.f, rs1 = 0.f;
#pragma unroll
        for (int nt = 0; nt < 8; nt++) {
            s[nt][0] = __expf(s[nt][0] - nm0); s[nt][1] = __expf(s[nt][1] - nm0);
            s[nt][2] = __expf(s[nt][2] - nm1); s[nt][3] = __expf(s[nt][3] - nm1);
            rs0 += s[nt][0] + s[nt][1];
            rs1 += s[nt][2] + s[nt][3];
        }
        rs0 += __shfl_xor_sync(0xffffffffu, rs0, 1);
        rs0 += __shfl_xor_sync(0xffffffffu, rs0, 2);
        rs1 += __shfl_xor_sync(0xffffffffu, rs1, 1);
        rs1 += __shfl_xor_sync(0xffffffffu, rs1, 2);
        l_i[0] = l_i[0] * corr0 + rs0; m_i[0] = nm0;
        l_i[1] = l_i[1] * corr1 + rs1; m_i[1] = nm1;
#pragma unroll
        for (int nt = 0; nt < 8; nt++) {
            o[nt][0] *= corr0; o[nt][1] *= corr0;
            o[nt][2] *= corr1; o[nt][3] *= corr1;
        }

        // --- PV: P acc frags -> A frags (hi/lo), V via ldmatrix.trans ---
#pragma unroll
        for (int kt = 0; kt < 4; kt++) {
            u32 Ph[4], Pl[4];
            pack_hilo(s[2 * kt][0],     s[2 * kt][1],     Ph[0], Pl[0]);
            pack_hilo(s[2 * kt][2],     s[2 * kt][3],     Ph[1], Pl[1]);
            pack_hilo(s[2 * kt + 1][0], s[2 * kt + 1][1], Ph[2], Pl[2]);
            pack_hilo(s[2 * kt + 1][2], s[2 * kt + 1][3], Ph[3], Pl[3]);
            const u32 voff_row = kt * 16 + (lane & 15);
#pragma unroll
            for (int nt = 0; nt < 8; nt++) {
                u32 vh[2], vl[2];
                const u32 off = (u32)SWZ(voff_row * 128 + nt * 16);
                ldm_x2t(vh, sVh + off);
                ldm_x2t(vl, sVl + off);
                mma_bf16(o[nt], Ph, vh);
                mma_bf16(o[nt], Ph, vl);
                mma_bf16(o[nt], Pl, vh);
            }
        }

        __syncthreads();
        if (kb + 2 < 32) {
            fa_load_stage(stg, Kh_, Kl_, Vh_, Vl_, kvbase + (size_t)(kb + 2) * 64 * HDIM, tid);
            cp_commit();
            if (tid < 64) mb[st][tid] = mask[(size_t)b * SS + (kb + 2) * 64 + tid] ? 0.f : -1e30f;
        }
    }

    // --- epilogue: normalize, split to bf16 hi/lo, write (B,S,E) ---
    const float inv0 = 1.f / l_i[0], inv1 = 1.f / l_i[1];
    const size_t row0 = (size_t)b * SS + q0 + w * 16 + (lane >> 2);
    const size_t row1 = row0 + 8;
#pragma unroll
    for (int nt = 0; nt < 8; nt++) {
        const int col = h * HDIM + nt * 8 + (lane & 3) * 2;
        u32 ph, pl;
        pack_hilo(o[nt][0] * inv0, o[nt][1] * inv0, ph, pl);
        *(u32*)&Ohi[row0 * EMB + col] = ph;
        *(u32*)&Olo[row0 * EMB + col] = pl;
        pack_hilo(o[nt][2] * inv1, o[nt][3] * inv1, ph, pl);
        *(u32*)&Ohi[row1 * EMB + col] = ph;
        *(u32*)&Olo[row1 * EMB + col] = pl;
    }
}

// ---------------- launch ----------------
extern "C" void kernel_launch(void* const* d_in, const int* in_sizes, int n_in,
                              void* d_out, int out_size)
{
    const float* query = (const float*)d_in[0];
    const float* key   = (const float*)d_in[1];
    const float* value = (const float*)d_in[2];
    const u32*   mask  = (const u32*)d_in[3];
    const float* Wq = (const float*)d_in[4];
    const float* bq = (const float*)d_in[5];
    const float* Wk = (const float*)d_in[6];
    const float* bk = (const float*)d_in[7];
    const float* Wv = (const float*)d_in[8];
    const float* bv = (const float*)d_in[9];
    const float* Wo = (const float*)d_in[10];
    const float* bo = (const float*)d_in[11];
    float* out = (float*)d_out;

    __nv_bfloat16 *ahi, *alo, *wthi, *wtlo, *qhi, *qlo, *khi, *klo, *vhi, *vlo;
    cudaGetSymbolAddress((void**)&ahi,  g_ahi);
    cudaGetSymbolAddress((void**)&alo,  g_alo);
    cudaGetSymbolAddress((void**)&wthi, g_wthi);
    cudaGetSymbolAddress((void**)&wtlo, g_wtlo);
    cudaGetSymbolAddress((void**)&qhi,  g_qhi);
    cudaGetSymbolAddress((void**)&qlo,  g_qlo);
    cudaGetSymbolAddress((void**)&khi,  g_khi);
    cudaGetSymbolAddress((void**)&klo,  g_klo);
    cudaGetSymbolAddress((void**)&vhi,  g_vhi);
    cudaGetSymbolAddress((void**)&vlo,  g_vlo);

    cudaFuncSetAttribute(gemm_mma,  cudaFuncAttributeMaxDynamicSharedMemorySize, GEMM_SMEM);
    cudaFuncSetAttribute(flash_mma, cudaFuncAttributeMaxDynamicSharedMemorySize, FA_SMEM);

    const dim3 ggrid(EMB / 128, MROWS / 128);   // (8, 64)
    const dim3 tgrid(EMB / 32, EMB / 32), tblk(32, 8);
    const int n4 = MROWS * EMB / 4;
    const float qscale = 0.125f;                // 1/sqrt(64)

    split_bf16<<<2048, 256>>>(query, ahi, alo, n4);
    transpose_split<<<tgrid, tblk>>>(Wq, wthi, wtlo);
    gemm_mma<<<ggrid, 256, GEMM_SMEM>>>(ahi, alo, wthi, wtlo, bq, nullptr, qhi, qlo, qscale, 1);

    split_bf16<<<2048, 256>>>(key, ahi, alo, n4);
    transpose_split<<<tgrid, tblk>>>(Wk, wthi, wtlo);
    gemm_mma<<<ggrid, 256, GEMM_SMEM>>>(ahi, alo, wthi, wtlo, bk, nullptr, khi, klo, 1.0f, 1);

    split_bf16<<<2048, 256>>>(value, ahi, alo, n4);
    transpose_split<<<tgrid, tblk>>>(Wv, wthi, wtlo);
    gemm_mma<<<ggrid, 256, GEMM_SMEM>>>(ahi, alo, wthi, wtlo, bv, nullptr, vhi, vlo, 1.0f, 1);

    // flash: writes attn directly as bf16 hi/lo into ahi/alo (B,S,E)
    flash_mma<<<dim3(SS / 128, BB * HEADS), 256, FA_SMEM>>>(
        qhi, qlo, khi, klo, vhi, vlo, mask, ahi, alo);

    transpose_split<<<tgrid, tblk>>>(Wo, wthi, wtlo);
    gemm_mma<<<ggrid, 256, GEMM_SMEM>>>(ahi, alo, wthi, wtlo, bo, out, nullptr, nullptr, 1.0f, 0);
}

// round 17
// speedup vs baseline: 1.3015x; 1.3015x over previous
#include <cuda_runtime.h>
#include <cuda_bf16.h>
#include <math.h>

#define BB 4
#define SS 2048
#define EMB 1024
#define HEADS 16
#define HDIM 64
#define MROWS (BB * SS)   // 8192

typedef unsigned long long u64;
typedef unsigned int u32;

#define SWZ(o) ((o) ^ (((o) >> 3) & 0x70))   // SW128 byte swizzle

// ---------------- baseline async + mma helpers (sm_103-safe) ----------------
__device__ __forceinline__ u32 smem_u32(const void* p) {
    u32 a; asm("{ .reg .u64 t; cvta.to.shared.u64 t, %1; cvt.u32.u64 %0, t; }" : "=r"(a) : "l"(p));
    return a;
}
__device__ __forceinline__ void cp16(u32 dst, const void* src) {
    asm volatile("cp.async.cg.shared.global [%0], [%1], 16;" :: "r"(dst), "l"(src) : "memory");
}
__device__ __forceinline__ void cp_commit() { asm volatile("cp.async.commit_group;" ::: "memory"); }
__device__ __forceinline__ void cp_wait2()  { asm volatile("cp.async.wait_group 2;"  ::: "memory"); }
__device__ __forceinline__ void cp_wait1()  { asm volatile("cp.async.wait_group 1;"  ::: "memory"); }
__device__ __forceinline__ void cp_wait0()  { asm volatile("cp.async.wait_group 0;"  ::: "memory"); }

__device__ __forceinline__ void ldm_x4(u32* r, u32 addr) {
    asm volatile("ldmatrix.sync.aligned.m8n8.x4.shared.b16 {%0,%1,%2,%3}, [%4];"
        : "=r"(r[0]), "=r"(r[1]), "=r"(r[2]), "=r"(r[3]) : "r"(addr));
}
__device__ __forceinline__ void ldm_x2(u32* r, u32 addr) {
    asm volatile("ldmatrix.sync.aligned.m8n8.x2.shared.b16 {%0,%1}, [%2];"
        : "=r"(r[0]), "=r"(r[1]) : "r"(addr));
}
__device__ __forceinline__ void ldm_x2t(u32* r, u32 addr) {
    asm volatile("ldmatrix.sync.aligned.m8n8.x2.trans.shared.b16 {%0,%1}, [%2];"
        : "=r"(r[0]), "=r"(r[1]) : "r"(addr));
}
__device__ __forceinline__ void mma_bf16(float* c, const u32* a, const u32* b) {
    asm volatile(
        "mma.sync.aligned.m16n8k16.row.col.f32.bf16.bf16.f32 "
        "{%0,%1,%2,%3}, {%4,%5,%6,%7}, {%8,%9}, {%0,%1,%2,%3};"
        : "+f"(c[0]), "+f"(c[1]), "+f"(c[2]), "+f"(c[3])
        : "r"(a[0]), "r"(a[1]), "r"(a[2]), "r"(a[3]), "r"(b[0]), "r"(b[1]));
}
// pack (s0, s1) -> bf16x2 hi + bf16x2 residual lo
__device__ __forceinline__ void pack_hilo(float s0, float s1, u32& ph, u32& pl) {
    u32 h; asm("cvt.rn.bf16x2.f32 %0, %1, %2;" : "=r"(h) : "f"(s1), "f"(s0));
    const float h0 = __uint_as_float(h << 16);
    const float h1 = __uint_as_float(h & 0xffff0000u);
    u32 l; asm("cvt.rn.bf16x2.f32 %0, %1, %2;" : "=r"(l) : "f"(s1 - h1), "f"(s0 - h0));
    ph = h; pl = l;
}

// ---------------- scratch ----------------
__device__ __nv_bfloat16 g_ahi[MROWS * EMB];
__device__ __nv_bfloat16 g_alo[MROWS * EMB];
__device__ __nv_bfloat16 g_wthi[EMB * EMB];
__device__ __nv_bfloat16 g_wtlo[EMB * EMB];
__device__ __nv_bfloat16 g_qhi[MROWS * EMB];
__device__ __nv_bfloat16 g_qlo[MROWS * EMB];
__device__ __nv_bfloat16 g_khi[MROWS * EMB];
__device__ __nv_bfloat16 g_klo[MROWS * EMB];
__device__ __nv_bfloat16 g_vhi[MROWS * EMB];
__device__ __nv_bfloat16 g_vlo[MROWS * EMB];
__device__ int g_kidx[BB * SS];
__device__ int g_kcnt[BB];

// ---------------- bf16 split preps ----------------
__device__ __forceinline__ unsigned short bfbits(float x) {
    __nv_bfloat16 h = __float2bfloat16(x);
    return reinterpret_cast<unsigned short&>(h);
}
__device__ __forceinline__ float bfval(unsigned short b) {
    __nv_bfloat16 h = reinterpret_cast<__nv_bfloat16&>(b);
    return __bfloat162float(h);
}

__global__ __launch_bounds__(256) void split_bf16(
    const float* __restrict__ x, __nv_bfloat16* __restrict__ hi,
    __nv_bfloat16* __restrict__ lo, int n4)
{
    int i = blockIdx.x * blockDim.x + threadIdx.x;
    const int stride = gridDim.x * blockDim.x;
    for (; i < n4; i += stride) {
        const float4 v = ((const float4*)x)[i];
        unsigned short h0 = bfbits(v.x), h1 = bfbits(v.y), h2 = bfbits(v.z), h3 = bfbits(v.w);
        unsigned short l0 = bfbits(v.x - bfval(h0)), l1 = bfbits(v.y - bfval(h1));
        unsigned short l2 = bfbits(v.z - bfval(h2)), l3 = bfbits(v.w - bfval(h3));
        ((uint2*)hi)[i] = make_uint2((u32)h0 | ((u32)h1 << 16), (u32)h2 | ((u32)h3 << 16));
        ((uint2*)lo)[i] = make_uint2((u32)l0 | ((u32)l1 << 16), (u32)l2 | ((u32)l3 << 16));
    }
}

__global__ void transpose_split(
    const float* __restrict__ W, __nv_bfloat16* __restrict__ hi,
    __nv_bfloat16* __restrict__ lo)
{
    __shared__ float t[32][33];
    const int k0 = blockIdx.y * 32, n0 = blockIdx.x * 32;
    const int x = threadIdx.x, y0 = threadIdx.y;
#pragma unroll
    for (int i = 0; i < 4; i++) t[y0 + i * 8][x] = W[(size_t)(k0 + y0 + i * 8) * EMB + n0 + x];
    __syncthreads();
#pragma unroll
    for (int i = 0; i < 4; i++) {
        const int nn = y0 + i * 8;
        const float v = t[x][nn];
        const unsigned short h = bfbits(v);
        const unsigned short l = bfbits(v - bfval(h));
        hi[(size_t)(n0 + nn) * EMB + k0 + x] = reinterpret_cast<const __nv_bfloat16&>(h);
        lo[(size_t)(n0 + nn) * EMB + k0 + x] = reinterpret_cast<const __nv_bfloat16&>(l);
    }
}

// Per-batch order-preserving compaction of unmasked key indices.
__global__ __launch_bounds__(256) void compact_mask(
    const u32* __restrict__ mask, int* __restrict__ kidx, int* __restrict__ kcnt)
{
    __shared__ int sc[256];
    const int b = blockIdx.x, t = threadIdx.x;
    const u32* mrow = mask + (size_t)b * SS;
    int loc[8], c = 0;
#pragma unroll
    for (int i = 0; i < 8; i++) {
        const int key = t * 8 + i;
        if (mrow[key]) loc[c++] = key;
    }
    sc[t] = c;
    __syncthreads();
    for (int d = 1; d < 256; d <<= 1) {          // Hillis-Steele inclusive scan
        const int add = (t >= d) ? sc[t - d] : 0;
        __syncthreads();
        sc[t] += add;
        __syncthreads();
    }
    int off = sc[t] - c;
    for (int i = 0; i < c; i++) kidx[b * SS + off + i] = loc[i];
    if (t == 255) kcnt[b] = sc[255];
}

// ---------------- mma.sync GEMM (bf16x3) ----------------
#define GEMM_NIT 16
#define STAGE_BYTES 65536
#define GEMM_SMEM (2 * STAGE_BYTES)

__device__ __forceinline__ void gemm_load_stage(
    u32 st, const __nv_bfloat16* __restrict__ Ahi, const __nv_bfloat16* __restrict__ Alo,
    const __nv_bfloat16* __restrict__ Bhi, const __nv_bfloat16* __restrict__ Blo,
    int m0, int n0, int k0, int tid)
{
#pragma unroll
    for (int i = 0; i < 4; i++) {
        const int c = tid + i * 256;
        const int row = c >> 3, col16 = c & 7;
        const u32 sw = (u32)SWZ(row * 128 + col16 * 16);
        const size_t ga = (size_t)(m0 + row) * EMB + k0 + col16 * 8;
        const size_t gb = (size_t)(n0 + row) * EMB + k0 + col16 * 8;
        cp16(st +     0 + sw, Ahi + ga);
        cp16(st + 16384 + sw, Alo + ga);
        cp16(st + 32768 + sw, Bhi + gb);
        cp16(st + 49152 + sw, Blo + gb);
    }
}

__global__ __launch_bounds__(256)
void gemm_mma(const __nv_bfloat16* __restrict__ Ahi, const __nv_bfloat16* __restrict__ Alo,
              const __nv_bfloat16* __restrict__ Bhi, const __nv_bfloat16* __restrict__ Blo,
              const float* __restrict__ bias, float* __restrict__ C,
              __nv_bfloat16* __restrict__ Chi, __nv_bfloat16* __restrict__ Clo,
              float scale, int split_mode)
{
    extern __shared__ __align__(1024) char smem[];
    const u32 sb = smem_u32(smem);
    const int tid = threadIdx.x;
    const int lane = tid & 31, wid = tid >> 5;
    const int wm = wid & 1, wn = wid >> 1;
    const int m0 = blockIdx.y * 128, n0 = blockIdx.x * 128;

    float acc[4][4][4];
#pragma unroll
    for (int mt = 0; mt < 4; mt++)
#pragma unroll
        for (int nt = 0; nt < 4; nt++)
#pragma unroll
            for (int e = 0; e < 4; e++) acc[mt][nt][e] = 0.f;

    const int a_row = (lane & 15), a_kb = (lane >> 4) * 16;
    const int b_row = (lane & 7),  b_kb = ((lane >> 3) & 1) * 16;

    gemm_load_stage(sb,               Ahi, Alo, Bhi, Blo, m0, n0, 0,  tid); cp_commit();
    gemm_load_stage(sb + STAGE_BYTES, Ahi, Alo, Bhi, Blo, m0, n0, 64, tid); cp_commit();

    for (int it = 0; it < GEMM_NIT; it++) {
        const u32 stg = sb + (it & 1) * STAGE_BYTES;
        if (it >= GEMM_NIT - 2) cp_wait0(); else cp_wait1();
        __syncthreads();

        const u32 sAh = stg, sAl = stg + 16384, sBh = stg + 32768, sBl = stg + 49152;
#pragma unroll
        for (int ks = 0; ks < 4; ks++) {
            u32 ah[4][4], al[4][4], bh[4][2], bl[4][2];
#pragma unroll
            for (int mt = 0; mt < 4; mt++) {
                const u32 off = (u32)SWZ((wm * 64 + mt * 16 + a_row) * 128 + ks * 32 + a_kb);
                ldm_x4(ah[mt], sAh + off);
                ldm_x4(al[mt], sAl + off);
            }
#pragma unroll
            for (int nt = 0; nt < 4; nt++) {
                const u32 off = (u32)SWZ((wn * 32 + nt * 8 + b_row) * 128 + ks * 32 + b_kb);
                ldm_x2(bh[nt], sBh + off);
                ldm_x2(bl[nt], sBl + off);
            }
#pragma unroll
            for (int mt = 0; mt < 4; mt++)
#pragma unroll
                for (int nt = 0; nt < 4; nt++) {
                    mma_bf16(acc[mt][nt], ah[mt], bh[nt]);
                    mma_bf16(acc[mt][nt], ah[mt], bl[nt]);
                    mma_bf16(acc[mt][nt], al[mt], bh[nt]);
                }
        }
        __syncthreads();
        if (it + 2 < GEMM_NIT) {
            gemm_load_stage(stg, Ahi, Alo, Bhi, Blo, m0, n0, (it + 2) * 64, tid);
            cp_commit();
        }
    }

#pragma unroll
    for (int mt = 0; mt < 4; mt++) {
        const int r0 = m0 + wm * 64 + mt * 16 + (lane >> 2);
#pragma unroll
        for (int nt = 0; nt < 4; nt++) {
            const int cc = n0 + wn * 32 + nt * 8 + (lane & 3) * 2;
            const float2 bb = *(const float2*)&bias[cc];
#pragma unroll
            for (int half = 0; half < 2; half++) {
                const int m = r0 + half * 8;
                const float v0 = (acc[mt][nt][half * 2 + 0] + bb.x) * scale;
                const float v1 = (acc[mt][nt][half * 2 + 1] + bb.y) * scale;
                if (split_mode) {   // bf16 hi/lo, (B,H,S,D) layout
                    const int b = m >> 11, s2 = m & 2047;
                    const int h = cc >> 6, dd = cc & 63;
                    u32 ph, pl; pack_hilo(v0, v1, ph, pl);
                    const size_t off = (((size_t)(b * HEADS + h) * SS) + s2) * HDIM + dd;
                    *(u32*)&Chi[off] = ph;
                    *(u32*)&Clo[off] = pl;
                } else {
                    *(float2*)&C[(size_t)m * EMB + cc] = make_float2(v0, v1);
                }
            }
        }
    }
}

// ---------------- flash attention via mma.sync (bf16x3, compacted keys) ----
// CTA: 128 q-rows x (b,h). 8 warps, warp w owns q rows [w*16, w*16+16).
// K/V rows gathered through per-batch compacted index list; only the ragged
// tail block needs a -1e30 bias.
#define FA_SMEM (32768 + 65536)

__device__ __forceinline__ void fa_load_stage(
    u32 st, const __nv_bfloat16* Kh, const __nv_bfloat16* Kl,
    const __nv_bfloat16* Vh, const __nv_bfloat16* Vl,
    size_t bhbase, const int* __restrict__ kidx_b, int cnt, int kb, int tid)
{
#pragma unroll
    for (int i = 0; i < 2; i++) {
        const int c = tid + i * 256;              // 0..511
        const int row = c >> 3, col16 = c & 7;
        int pos = kb * 64 + row;
        if (pos >= cnt) pos = cnt - 1;            // clamp (bias kills tail)
        const int key = kidx_b[pos];
        const u32 sw = (u32)SWZ(row * 128 + col16 * 16);
        const size_t g = bhbase + (size_t)key * HDIM + col16 * 8;
        cp16(st +     0 + sw, Kh + g);
        cp16(st +  8192 + sw, Kl + g);
        cp16(st + 16384 + sw, Vh + g);
        cp16(st + 24576 + sw, Vl + g);
    }
}

__global__ __launch_bounds__(256, 1)
void flash_mma(const __nv_bfloat16* __restrict__ Qh_, const __nv_bfloat16* __restrict__ Ql_,
               const __nv_bfloat16* __restrict__ Kh_, const __nv_bfloat16* __restrict__ Kl_,
               const __nv_bfloat16* __restrict__ Vh_, const __nv_bfloat16* __restrict__ Vl_,
               const int* __restrict__ kidx, const int* __restrict__ kcnt,
               __nv_bfloat16* __restrict__ Ohi, __nv_bfloat16* __restrict__ Olo)
{
    extern __shared__ __align__(1024) char smem[];
    __shared__ float mb[2][64];
    const u32 sb = smem_u32(smem);
    const int tid = threadIdx.x;
    const int lane = tid & 31, w = tid >> 5;
    const int bh = blockIdx.y, b = bh >> 4, h = bh & 15;
    const int q0 = blockIdx.x * 128;

    const int cnt = kcnt[b];
    const int nkb = (cnt + 63) >> 6;
    const int* kidx_b = kidx + (size_t)b * SS;

    const size_t qbase  = ((size_t)bh * SS + q0) * HDIM;
    const size_t kvbase = (size_t)bh * SS * HDIM;
    const u32 sQh = sb, sQl = sb + 16384;
    const u32 stg0 = sb + 32768, stg1 = sb + 65536;

    // Q tile loads (hi+lo)
#pragma unroll
    for (int i = 0; i < 4; i++) {
        const int c = tid + i * 256;
        const int row = c >> 3, col16 = c & 7;
        const u32 sw = (u32)SWZ(row * 128 + col16 * 16);
        const size_t g = qbase + (size_t)row * HDIM + col16 * 8;
        cp16(sQh + sw, Qh_ + g);
        cp16(sQl + sw, Ql_ + g);
    }
    cp_commit();
    fa_load_stage(stg0, Kh_, Kl_, Vh_, Vl_, kvbase, kidx_b, cnt, 0, tid); cp_commit();
    if (tid < 64) mb[0][tid] = (tid < cnt) ? 0.f : -1e30f;
    fa_load_stage(stg1, Kh_, Kl_, Vh_, Vl_, kvbase, kidx_b, cnt, 1, tid); cp_commit();
    if (tid < 64) mb[1][tid] = (64 + tid < cnt) ? 0.f : -1e30f;

    cp_wait2();     // Q group done
    __syncthreads();

    // Q fragments (loop-invariant)
    u32 qh[4][4], ql[4][4];
    const int a_row = (lane & 15), a_kb = (lane >> 4) * 16;
#pragma unroll
    for (int ks = 0; ks < 4; ks++) {
        const u32 off = (u32)SWZ((w * 16 + a_row) * 128 + ks * 32 + a_kb);
        ldm_x4(qh[ks], sQh + off);
        ldm_x4(ql[ks], sQl + off);
    }

    float m_i[2] = { -INFINITY, -INFINITY }, l_i[2] = { 0.f, 0.f };
    float o[8][4];
#pragma unroll
    for (int nt = 0; nt < 8; nt++)
#pragma unroll
        for (int e = 0; e < 4; e++) o[nt][e] = 0.f;

    const int b_row = (lane & 7), b_kb = ((lane >> 3) & 1) * 16;

    for (int kb = 0; kb < nkb; kb++) {
        const int st = kb & 1;
        const u32 stg = st ? stg1 : stg0;
        if (kb >= nkb - 2) cp_wait0(); else cp_wait1();
        __syncthreads();

        const u32 sKh = stg, sKl = stg + 8192, sVh = stg + 16384, sVl = stg + 24576;

        // --- QK^T (3-pass bf16x3) ---
        float s[8][4];
#pragma unroll
        for (int nt = 0; nt < 8; nt++)
#pragma unroll
            for (int e = 0; e < 4; e++) s[nt][e] = 0.f;

#pragma unroll
        for (int ks = 0; ks < 4; ks++) {
            u32 kh[8][2], kl[8][2];
#pragma unroll
            for (int nt = 0; nt < 8; nt++) {
                const u32 off = (u32)SWZ((nt * 8 + b_row) * 128 + ks * 32 + b_kb);
                ldm_x2(kh[nt], sKh + off);
                ldm_x2(kl[nt], sKl + off);
            }
#pragma unroll
            for (int nt = 0; nt < 8; nt++) {
                mma_bf16(s[nt], qh[ks], kh[nt]);
                mma_bf16(s[nt], qh[ks], kl[nt]);
                mma_bf16(s[nt], ql[ks], kh[nt]);
            }
        }

        // --- tail bias ---
#pragma unroll
        for (int nt = 0; nt < 8; nt++) {
            const int kc = nt * 8 + (lane & 3) * 2;
            const float c0 = mb[st][kc], c1 = mb[st][kc + 1];
            s[nt][0] += c0; s[nt][1] += c1; s[nt][2] += c0; s[nt][3] += c1;
        }

        // --- online softmax ---
        float rm0 = -INFINITY, rm1 = -INFINITY;
#pragma unroll
        for (int nt = 0; nt < 8; nt++) {
            rm0 = fmaxf(rm0, fmaxf(s[nt][0], s[nt][1]));
            rm1 = fmaxf(rm1, fmaxf(s[nt][2], s[nt][3]));
        }
        rm0 = fmaxf(rm0, __shfl_xor_sync(0xffffffffu, rm0, 1));
        rm0 = fmaxf(rm0, __shfl_xor_sync(0xffffffffu, rm0, 2));
        rm1 = fmaxf(rm1, __shfl_xor_sync(0xffffffffu, rm1, 1));
        rm1 = fmaxf(rm1, __shfl_xor_sync(0xffffffffu, rm1, 2));
        const float nm0 = fmaxf(m_i[0], rm0), nm1 = fmaxf(m_i[1], rm1);
        const float corr0 = __expf(m_i[0] - nm0), corr1 = __expf(m_i[1] - nm1);
        float rs0 = 0.f, rs1 = 0.f;
#pragma unroll
        for (int nt = 0; nt < 8; nt++) {
            s[nt][0] = __expf(s[nt][0] - nm0); s[nt][1] = __expf(s[nt][1] - nm0);
            s[nt][2] = __expf(s[nt][2] - nm1); s[nt][3] = __expf(s[nt][3] - nm1);
            rs0 += s[nt][0] + s[nt][1];
            rs1 += s[nt][2] + s[nt][3];
        }
        rs0 += __shfl_xor_sync(0xffffffffu, rs0, 1);
        rs0 += __shfl_xor_sync(0xffffffffu, rs0, 2);
        rs1 += __shfl_xor_sync(0xffffffffu, rs1, 1);
        rs1 += __shfl_xor_sync(0xffffffffu, rs1, 2);
        l_i[0] = l_i[0] * corr0 + rs0; m_i[0] = nm0;
        l_i[1] = l_i[1] * corr1 + rs1; m_i[1] = nm1;
#pragma unroll
        for (int nt = 0; nt < 8; nt++) {
            o[nt][0] *= corr0; o[nt][1] *= corr0;
            o[nt][2] *= corr1; o[nt][3] *= corr1;
        }

        // --- PV ---
#pragma unroll
        for (int kt = 0; kt < 4; kt++) {
            u32 Ph[4], Pl[4];
            pack_hilo(s[2 * kt][0],     s[2 * kt][1],     Ph[0], Pl[0]);
            pack_hilo(s[2 * kt][2],     s[2 * kt][3],     Ph[1], Pl[1]);
            pack_hilo(s[2 * kt + 1][0], s[2 * kt + 1][1], Ph[2], Pl[2]);
            pack_hilo(s[2 * kt + 1][2], s[2 * kt + 1][3], Ph[3], Pl[3]);
            const u32 voff_row = kt * 16 + (lane & 15);
#pragma unroll
            for (int nt = 0; nt < 8; nt++) {
                u32 vh[2], vl[2];
                const u32 off = (u32)SWZ(voff_row * 128 + nt * 16);
                ldm_x2t(vh, sVh + off);
                ldm_x2t(vl, sVl + off);
                mma_bf16(o[nt], Ph, vh);
                mma_bf16(o[nt], Ph, vl);
                mma_bf16(o[nt], Pl, vh);
            }
        }

        __syncthreads();
        if (kb + 2 < nkb) {
            fa_load_stage(stg, Kh_, Kl_, Vh_, Vl_, kvbase, kidx_b, cnt, kb + 2, tid);
            cp_commit();
            if (tid < 64) mb[st][tid] = ((kb + 2) * 64 + tid < cnt) ? 0.f : -1e30f;
        }
    }

    // --- epilogue: normalize, split to bf16 hi/lo, write (B,S,E) ---
    const float inv0 = 1.f / l_i[0], inv1 = 1.f / l_i[1];
    const size_t row0 = (size_t)b * SS + q0 + w * 16 + (lane >> 2);
    const size_t row1 = row0 + 8;
#pragma unroll
    for (int nt = 0; nt < 8; nt++) {
        const int col = h * HDIM + nt * 8 + (lane & 3) * 2;
        u32 ph, pl;
        pack_hilo(o[nt][0] * inv0, o[nt][1] * inv0, ph, pl);
        *(u32*)&Ohi[row0 * EMB + col] = ph;
        *(u32*)&Olo[row0 * EMB + col] = pl;
        pack_hilo(o[nt][2] * inv1, o[nt][3] * inv1, ph, pl);
        *(u32*)&Ohi[row1 * EMB + col] = ph;
        *(u32*)&Olo[row1 * EMB + col] = pl;
    }
}

// ---------------- launch ----------------
extern "C" void kernel_launch(void* const* d_in, const int* in_sizes, int n_in,
                              void* d_out, int out_size)
{
    const float* query = (const float*)d_in[0];
    const float* key   = (const float*)d_in[1];
    const float* value = (const float*)d_in[2];
    const u32*   mask  = (const u32*)d_in[3];
    const float* Wq = (const float*)d_in[4];
    const float* bq = (const float*)d_in[5];
    const float* Wk = (const float*)d_in[6];
    const float* bk = (const float*)d_in[7];
    const float* Wv = (const float*)d_in[8];
    const float* bv = (const float*)d_in[9];
    const float* Wo = (const float*)d_in[10];
    const float* bo = (const float*)d_in[11];
    float* out = (float*)d_out;

    __nv_bfloat16 *ahi, *alo, *wthi, *wtlo, *qhi, *qlo, *khi, *klo, *vhi, *vlo;
    int *kidx, *kcnt;
    cudaGetSymbolAddress((void**)&ahi,  g_ahi);
    cudaGetSymbolAddress((void**)&alo,  g_alo);
    cudaGetSymbolAddress((void**)&wthi, g_wthi);
    cudaGetSymbolAddress((void**)&wtlo, g_wtlo);
    cudaGetSymbolAddress((void**)&qhi,  g_qhi);
    cudaGetSymbolAddress((void**)&qlo,  g_qlo);
    cudaGetSymbolAddress((void**)&khi,  g_khi);
    cudaGetSymbolAddress((void**)&klo,  g_klo);
    cudaGetSymbolAddress((void**)&vhi,  g_vhi);
    cudaGetSymbolAddress((void**)&vlo,  g_vlo);
    cudaGetSymbolAddress((void**)&kidx, g_kidx);
    cudaGetSymbolAddress((void**)&kcnt, g_kcnt);

    cudaFuncSetAttribute(gemm_mma,  cudaFuncAttributeMaxDynamicSharedMemorySize, GEMM_SMEM);
    cudaFuncSetAttribute(flash_mma, cudaFuncAttributeMaxDynamicSharedMemorySize, FA_SMEM);

    const dim3 ggrid(EMB / 128, MROWS / 128);   // (8, 64)
    const dim3 tgrid(EMB / 32, EMB / 32), tblk(32, 8);
    const int n4 = MROWS * EMB / 4;
    const float qscale = 0.125f;                // 1/sqrt(64)

    compact_mask<<<BB, 256>>>(mask, kidx, kcnt);

    split_bf16<<<2048, 256>>>(query, ahi, alo, n4);
    transpose_split<<<tgrid, tblk>>>(Wq, wthi, wtlo);
    gemm_mma<<<ggrid, 256, GEMM_SMEM>>>(ahi, alo, wthi, wtlo, bq, nullptr, qhi, qlo, qscale, 1);

    split_bf16<<<2048, 256>>>(key, ahi, alo, n4);
    transpose_split<<<tgrid, tblk>>>(Wk, wthi, wtlo);
    gemm_mma<<<ggrid, 256, GEMM_SMEM>>>(ahi, alo, wthi, wtlo, bk, nullptr, khi, klo, 1.0f, 1);

    split_bf16<<<2048, 256>>>(value, ahi, alo, n4);
    transpose_split<<<tgrid, tblk>>>(Wv, wthi, wtlo);
    gemm_mma<<<ggrid, 256, GEMM_SMEM>>>(ahi, alo, wthi, wtlo, bv, nullptr, vhi, vlo, 1.0f, 1);

    // flash: writes attn directly as bf16 hi/lo into ahi/alo (B,S,E)
    flash_mma<<<dim3(SS / 128, BB * HEADS), 256, FA_SMEM>>>(
        qhi, qlo, khi, klo, vhi, vlo, kidx, kcnt, ahi, alo);

    transpose_split<<<tgrid, tblk>>>(Wo, wthi, wtlo);
    gemm_mma<<<ggrid, 256, GEMM_SMEM>>>(ahi, alo, wthi, wtlo, bo, out, nullptr, nullptr, 1.0f, 0);
}